// round 9
// baseline (speedup 1.0000x reference)
#include <cuda_runtime.h>
#include <cuda_fp16.h>
#include <stdint.h>
#include <math.h>

// Problem constants
#define Bb  2
#define Ss  4096
#define Dd  768
#define Hh  12
#define DHh 64

#define LOG2E 1.44269504088896341f

// Scratch (device globals)
__device__ __half g_Q[(size_t)Bb * Hh * Ss * DHh];
__device__ __half g_K[(size_t)Bb * Hh * Ss * DHh];
__device__ __half g_V[(size_t)Bb * Hh * Ss * DHh];
__device__ __half g_AO[(size_t)Bb * Ss * Dd];
__device__ __half g_X[(size_t)Bb * Ss * Dd];          // seq in half
__device__ __half g_Wh[4][(size_t)Dd * Dd];           // Wq,Wk,Wv,Wo in half
__device__ __half g_maskh[(size_t)Ss * Ss];           // mask in half

// ---------------------------------------------------------------------------
__device__ __forceinline__ uint32_t sptr(const void* p) {
    return (uint32_t)__cvta_generic_to_shared(p);
}
__device__ __forceinline__ void ldsm4(uint32_t a, uint32_t* r) {
    asm volatile("ldmatrix.sync.aligned.m8n8.x4.shared.b16 {%0,%1,%2,%3}, [%4];"
                 : "=r"(r[0]), "=r"(r[1]), "=r"(r[2]), "=r"(r[3]) : "r"(a));
}
__device__ __forceinline__ void ldsm4t(uint32_t a, uint32_t* r) {
    asm volatile("ldmatrix.sync.aligned.m8n8.x4.trans.shared.b16 {%0,%1,%2,%3}, [%4];"
                 : "=r"(r[0]), "=r"(r[1]), "=r"(r[2]), "=r"(r[3]) : "r"(a));
}
__device__ __forceinline__ void mma16(float* d, const uint32_t* a, const uint32_t* b) {
    asm volatile("mma.sync.aligned.m16n8k16.row.col.f32.f16.f16.f32 "
                 "{%0,%1,%2,%3}, {%4,%5,%6,%7}, {%8,%9}, {%0,%1,%2,%3};"
                 : "+f"(d[0]), "+f"(d[1]), "+f"(d[2]), "+f"(d[3])
                 : "r"(a[0]), "r"(a[1]), "r"(a[2]), "r"(a[3]),
                   "r"(b[0]), "r"(b[1]));
}
__device__ __forceinline__ uint32_t pack2(float x, float y) {
    __half2 h = __floats2half2_rn(x, y);
    return *(uint32_t*)&h;
}
__device__ __forceinline__ uint32_t h2exp2(uint32_t x) {
    uint32_t r;
    asm("ex2.approx.f16x2 %0, %1;" : "=r"(r) : "r"(x));
    return r;
}
__device__ __forceinline__ void cp16(uint32_t s, const void* g) {
    asm volatile("cp.async.cg.shared.global [%0], [%1], 16;" :: "r"(s), "l"(g));
}
#define CP_COMMIT() asm volatile("cp.async.commit_group;")
#define CP_WAIT1()  asm volatile("cp.async.wait_group 1;")

// ---------------------------------------------------------------------------
// fp32 -> fp16 conversions
// ---------------------------------------------------------------------------
__global__ void cvt_f2h(const float4* __restrict__ in, __half2* __restrict__ out,
                        int n4)
{
    for (int i = blockIdx.x * blockDim.x + threadIdx.x; i < n4;
         i += gridDim.x * blockDim.x) {
        float4 v = in[i];
        out[2 * i]     = __floats2half2_rn(v.x, v.y);
        out[2 * i + 1] = __floats2half2_rn(v.z, v.w);
    }
}
__global__ void cvt_w4(const float4* __restrict__ w0, const float4* __restrict__ w1,
                       const float4* __restrict__ w2, const float4* __restrict__ w3,
                       __half2* __restrict__ out, int n4)
{
    const float4* src = (blockIdx.y == 0) ? w0 : (blockIdx.y == 1) ? w1
                       : (blockIdx.y == 2) ? w2 : w3;
    __half2* dst = out + (size_t)blockIdx.y * n4 * 2;
    for (int i = blockIdx.x * blockDim.x + threadIdx.x; i < n4;
         i += gridDim.x * blockDim.x) {
        float4 v = src[i];
        dst[2 * i]     = __floats2half2_rn(v.x, v.y);
        dst[2 * i + 1] = __floats2half2_rn(v.z, v.w);
    }
}

// ---------------------------------------------------------------------------
// fp16 GEMM, pure cp.async staging (unchanged, proven)
// ---------------------------------------------------------------------------
#define GKLD 72
#define GSZ (128 * GKLD)
#define GEMM_DSMEM (2 * 2 * GSZ * 2)
#define GNK (Dd / 64)

__device__ __forceinline__ void gemm_body(
    const __half* __restrict__ X, const __half* __restrict__ W,
    const float* __restrict__ bias,
    float* __restrict__ outf, __half* __restrict__ outh,
    float alpha, int mode, int m0, int n0, __half* dsm)
{
    const int tid = threadIdx.x, lane = tid & 31, wp = tid >> 5;
    const int wm = (wp >> 2) * 64, wn = (wp & 3) * 32;

    int row[4], col[4];
#pragma unroll
    for (int c = 0; c < 4; c++) {
        int idx = c * 256 + tid;
        row[c] = idx >> 3; col[c] = (idx & 7) * 8;
    }
    const __half* Xg = X + (size_t)m0 * Dd;
    const __half* Wg = W + (size_t)n0 * Dd;

    uint32_t adst[2][4], bdst[2][4];
#pragma unroll
    for (int st = 0; st < 2; st++)
#pragma unroll
        for (int c = 0; c < 4; c++) {
            adst[st][c] = sptr(dsm + st * 2 * GSZ + row[c] * GKLD + col[c]);
            bdst[st][c] = sptr(dsm + st * 2 * GSZ + GSZ + row[c] * GKLD + col[c]);
        }

    float acc[4][4][4];
#pragma unroll
    for (int i = 0; i < 4; i++)
#pragma unroll
        for (int j = 0; j < 4; j++)
#pragma unroll
            for (int r = 0; r < 4; r++) acc[i][j][r] = 0.f;

    const int arow = wm + (lane & 15);
    const int acol = (lane & 16) ? 8 : 0;
    const int brow = wn + (lane & 7) + ((lane & 16) ? 8 : 0);
    const int bcol = (lane & 8) ? 8 : 0;
    uint32_t xsb[2], wsb[2];
#pragma unroll
    for (int st = 0; st < 2; st++) {
        xsb[st] = sptr(dsm + st * 2 * GSZ) + (uint32_t)((arow * GKLD + acol) * 2);
        wsb[st] = sptr(dsm + st * 2 * GSZ + GSZ) + (uint32_t)((brow * GKLD + bcol) * 2);
    }

#pragma unroll
    for (int c = 0; c < 4; c++) {
        cp16(adst[0][c], Xg + (size_t)row[c] * Dd + col[c]);
        cp16(bdst[0][c], Wg + (size_t)row[c] * Dd + col[c]);
    }
    CP_COMMIT();

    for (int step = 0; step < GNK; step++) {
        const int cur = step & 1;
        if (step + 1 < GNK) {
            const int k0 = (step + 1) * 64;
#pragma unroll
            for (int c = 0; c < 4; c++) {
                cp16(adst[cur ^ 1][c], Xg + (size_t)row[c] * Dd + k0 + col[c]);
                cp16(bdst[cur ^ 1][c], Wg + (size_t)row[c] * Dd + k0 + col[c]);
            }
        }
        CP_COMMIT();
        CP_WAIT1();
        __syncthreads();

#pragma unroll
        for (int s = 0; s < 4; s++) {
            uint32_t af[4][4];
#pragma unroll
            for (int i = 0; i < 4; i++)
                ldsm4(xsb[cur] + (uint32_t)((16 * i * GKLD + 16 * s) * 2), af[i]);
#pragma unroll
            for (int g = 0; g < 2; g++) {
                uint32_t bf[4];
                ldsm4(wsb[cur] + (uint32_t)((16 * g * GKLD + 16 * s) * 2), bf);
#pragma unroll
                for (int i = 0; i < 4; i++) {
                    mma16(acc[i][2 * g],     af[i], bf);
                    mma16(acc[i][2 * g + 1], af[i], bf + 2);
                }
            }
        }
        __syncthreads();
    }

    const int mr = m0 + wm + (lane >> 2);
    const int nc = n0 + wn + 2 * (lane & 3);
#pragma unroll
    for (int j = 0; j < 4; j++) {
        const int n = nc + 8 * j;
        const float bv0 = bias[n], bv1 = bias[n + 1];
#pragma unroll
        for (int i = 0; i < 4; i++) {
            const int m = mr + 16 * i;
            const float r00 = alpha * (acc[i][j][0] + bv0);
            const float r01 = alpha * (acc[i][j][1] + bv1);
            const float r10 = alpha * (acc[i][j][2] + bv0);
            const float r11 = alpha * (acc[i][j][3] + bv1);
            if (mode == 0) {
                const int bb = m >> 12, ss = m & 4095, hh = n >> 6, dh = n & 63;
                __half* p = outh + ((size_t)(bb * Hh + hh) * Ss + ss) * DHh + dh;
                *(__half2*)p = __floats2half2_rn(r00, r01);
                *(__half2*)(p + 8 * DHh) = __floats2half2_rn(r10, r11);
            } else {
                float* p = outf + (size_t)m * Dd + n;
                *(float2*)p = make_float2(r00, r01);
                *(float2*)(p + 8 * Dd) = make_float2(r10, r11);
            }
        }
    }
}

__global__ void __launch_bounds__(256, 2) gemm_qkv(
    const __half* __restrict__ X,
    const float* __restrict__ bq, const float* __restrict__ bk,
    const float* __restrict__ bv,
    __half* __restrict__ Qo, __half* __restrict__ Ko, __half* __restrict__ Vo)
{
    extern __shared__ __half dsm[];
    const int sel = blockIdx.x / 6;
    const int n0 = (blockIdx.x % 6) * 128;
    const int m0 = blockIdx.y * 128;
    const __half* W = g_Wh[sel];
    const float* bias = (sel == 0) ? bq : (sel == 1) ? bk : bv;
    __half* out = (sel == 0) ? Qo : (sel == 1) ? Ko : Vo;
    const float alpha = (sel == 0) ? 0.125f * LOG2E : 1.0f;
    gemm_body(X, W, bias, nullptr, out, alpha, 0, m0, n0, dsm);
}

__global__ void __launch_bounds__(256, 2) gemm_out(
    const __half* __restrict__ X, const float* __restrict__ bias,
    float* __restrict__ out)
{
    extern __shared__ __half dsm[];
    gemm_body(X, g_Wh[3], bias, out, nullptr, 1.0f, 1,
              blockIdx.y * 128, blockIdx.x * 128, dsm);
}

// ---------------------------------------------------------------------------
// fp16 flash attention: FA2 layout (4 warps x 32 Q rows), now 4 CTAs/SM.
// grid (bh, q_tile) so CTAs sharing mask rows are scheduled together.
// cp.async double-buffered K/V; half2 approx exp; row sums via ones-column MMA.
// ---------------------------------------------------------------------------
#define KLD 88
#define TILE_H (64 * KLD)

__global__ void __launch_bounds__(128, 4) flash_f16(
    const __half* __restrict__ Q, const __half* __restrict__ K,
    const __half* __restrict__ V, const __half* __restrict__ mask,
    __half* __restrict__ AO)
{
    __shared__ __half sm[2][2][TILE_H];

    const int tid = threadIdx.x, lane = tid & 31, wp = tid >> 5;
    const int bh = blockIdx.x;                  // swapped: bh fastest
    const int q0 = blockIdx.y * 128;
    const int b = bh / Hh, h = bh - b * Hh;

    const __half* Qp = Q + ((size_t)bh * Ss + q0) * DHh;
    const __half* Kp = K + (size_t)bh * Ss * DHh;
    const __half* Vp = V + (size_t)bh * Ss * DHh;

    // ---- Stage Q tile, load A-frags ----
    {
        __half* qstage = &sm[0][0][0];
#pragma unroll
        for (int c = 0; c < 8; c++) {
            int idx = c * 128 + tid;
            int r = idx >> 3, ch = (idx & 7) * 8;
            *(uint4*)&qstage[r * KLD + ch] = *(const uint4*)(Qp + (size_t)r * DHh + ch);
        }
    }
    __syncthreads();

    uint32_t qf[2][4][4];
#pragma unroll
    for (int t = 0; t < 2; t++) {
        const uint32_t qb = sptr(&sm[0][0][0]) +
            (uint32_t)(((32 * wp + 16 * t + (lane & 15)) * KLD +
                        ((lane & 16) ? 8 : 0)) * 2);
#pragma unroll
        for (int s = 0; s < 4; s++) ldsm4(qb + (uint32_t)(16 * s * 2), qf[t][s]);
    }
    __syncthreads();

    // ---- Init ones-column region of V buffers (cols 64..79, both stages) ----
    {
        const int st = tid >> 6, r = tid & 63;
        __half2* p = (__half2*)&sm[st][1][r * KLD + 64];
        p[0] = __floats2half2_rn(1.f, 0.f);
#pragma unroll
        for (int j = 1; j < 8; j++) p[j] = __floats2half2_rn(0.f, 0.f);
    }

    int srow[4], scol[4];
#pragma unroll
    for (int c = 0; c < 4; c++) {
        int idx = c * 128 + tid;
        srow[c] = idx >> 3; scol[c] = (idx & 7) * 8;
    }
    uint32_t kdst[2][4], vdst[2][4];
#pragma unroll
    for (int st = 0; st < 2; st++)
#pragma unroll
        for (int c = 0; c < 4; c++) {
            kdst[st][c] = sptr(&sm[st][0][srow[c] * KLD + scol[c]]);
            vdst[st][c] = sptr(&sm[st][1][srow[c] * KLD + scol[c]]);
        }

    const int krow = (lane & 7) + ((lane & 16) ? 8 : 0);
    const int kcol = (lane & 8) ? 8 : 0;
    const int vrow = lane & 15;
    const int vcol = (lane & 16) ? 8 : 0;
    uint32_t ksb[2], vsb[2];
#pragma unroll
    for (int st = 0; st < 2; st++) {
        ksb[st] = sptr(&sm[st][0][0]) + (uint32_t)((krow * KLD + kcol) * 2);
        vsb[st] = sptr(&sm[st][1][0]) + (uint32_t)((vrow * KLD + vcol) * 2);
    }

    float O[2][8][4];
    float Osum[2][4];
#pragma unroll
    for (int t = 0; t < 2; t++) {
#pragma unroll
        for (int j = 0; j < 8; j++)
#pragma unroll
            for (int r = 0; r < 4; r++) O[t][j][r] = 0.f;
#pragma unroll
        for (int r = 0; r < 4; r++) Osum[t][r] = 0.f;
    }
    float mr[2][2] = {{-1e30f, -1e30f}, {-1e30f, -1e30f}};

    const int pcol = 2 * (lane & 3);
    const __half* mbase[2];
#pragma unroll
    for (int t = 0; t < 2; t++)
        mbase[t] = mask + (size_t)(q0 + 32 * wp + 16 * t + (lane >> 2)) * Ss + pcol;

    const int NT = Ss / 64;

#pragma unroll
    for (int c = 0; c < 4; c++) {
        cp16(kdst[0][c], Kp + (size_t)srow[c] * DHh + scol[c]);
        cp16(vdst[0][c], Vp + (size_t)srow[c] * DHh + scol[c]);
    }
    CP_COMMIT();

    for (int kt = 0; kt < NT; kt++) {
        const int cur = kt & 1;
        if (kt + 1 < NT) {
            const __half* Kn = Kp + (size_t)(kt + 1) * 64 * DHh;
            const __half* Vn = Vp + (size_t)(kt + 1) * 64 * DHh;
#pragma unroll
            for (int c = 0; c < 4; c++) {
                cp16(kdst[cur ^ 1][c], Kn + (size_t)srow[c] * DHh + scol[c]);
                cp16(vdst[cur ^ 1][c], Vn + (size_t)srow[c] * DHh + scol[c]);
            }
        }
        CP_COMMIT();
        CP_WAIT1();
        __syncthreads();

        // ---- Scores ----
        float sc[2][8][4];
#pragma unroll
        for (int t = 0; t < 2; t++)
#pragma unroll
            for (int j = 0; j < 8; j++)
#pragma unroll
                for (int r = 0; r < 4; r++) sc[t][j][r] = 0.f;

        {
            uint32_t bf[2][4];
            ldsm4(ksb[cur], bf[0]);
#pragma unroll
            for (int i = 0; i < 16; i++) {
                const int s = i >> 2, g = i & 3;
                if (i + 1 < 16) {
                    const int s2 = (i + 1) >> 2, g2 = (i + 1) & 3;
                    ldsm4(ksb[cur] + (uint32_t)((16 * g2 * KLD + 16 * s2) * 2),
                          bf[(i + 1) & 1]);
                }
                mma16(sc[0][2 * g],     qf[0][s], bf[i & 1]);
                mma16(sc[0][2 * g + 1], qf[0][s], bf[i & 1] + 2);
                mma16(sc[1][2 * g],     qf[1][s], bf[i & 1]);
                mma16(sc[1][2 * g + 1], qf[1][s], bf[i & 1] + 2);
            }
        }

        // ---- Mask + online softmax (half2 approx exp; sums via PV MMA) ----
        uint32_t pf[2][4][4];
#pragma unroll
        for (int t = 0; t < 2; t++) {
            const __half* mp = mbase[t] + kt * 64;
#pragma unroll
            for (int j = 0; j < 8; j++) {
                float2 m0v = __half22float2(*(const __half2*)(mp + 8 * j));
                float2 m1v = __half22float2(*(const __half2*)(mp + 8 * (size_t)Ss + 8 * j));
                sc[t][j][0] = fmaf(m0v.x, LOG2E, sc[t][j][0]);
                sc[t][j][1] = fmaf(m0v.y, LOG2E, sc[t][j][1]);
                sc[t][j][2] = fmaf(m1v.x, LOG2E, sc[t][j][2]);
                sc[t][j][3] = fmaf(m1v.y, LOG2E, sc[t][j][3]);
            }

            float mx0 = -1e30f, mx1 = -1e30f;
#pragma unroll
            for (int j = 0; j < 8; j++) {
                mx0 = fmaxf(mx0, fmaxf(sc[t][j][0], sc[t][j][1]));
                mx1 = fmaxf(mx1, fmaxf(sc[t][j][2], sc[t][j][3]));
            }
            mx0 = fmaxf(mx0, __shfl_xor_sync(0xffffffffu, mx0, 1));
            mx0 = fmaxf(mx0, __shfl_xor_sync(0xffffffffu, mx0, 2));
            mx1 = fmaxf(mx1, __shfl_xor_sync(0xffffffffu, mx1, 1));
            mx1 = fmaxf(mx1, __shfl_xor_sync(0xffffffffu, mx1, 2));
            const float mn0 = fmaxf(mr[t][0], mx0), mn1 = fmaxf(mr[t][1], mx1);
            const float s0 = exp2f(mr[t][0] - mn0), s1 = exp2f(mr[t][1] - mn1);
            mr[t][0] = mn0; mr[t][1] = mn1;

#pragma unroll
            for (int s = 0; s < 4; s++) {
                pf[t][s][0] = h2exp2(pack2(sc[t][2 * s][0] - mn0,
                                           sc[t][2 * s][1] - mn0));
                pf[t][s][1] = h2exp2(pack2(sc[t][2 * s][2] - mn1,
                                           sc[t][2 * s][3] - mn1));
                pf[t][s][2] = h2exp2(pack2(sc[t][2 * s + 1][0] - mn0,
                                           sc[t][2 * s + 1][1] - mn0));
                pf[t][s][3] = h2exp2(pack2(sc[t][2 * s + 1][2] - mn1,
                                           sc[t][2 * s + 1][3] - mn1));
            }

#pragma unroll
            for (int j = 0; j < 8; j++) {
                O[t][j][0] *= s0; O[t][j][1] *= s0;
                O[t][j][2] *= s1; O[t][j][3] *= s1;
            }
            Osum[t][0] *= s0; Osum[t][1] *= s0;
            Osum[t][2] *= s1; Osum[t][3] *= s1;
        }

        // ---- O += P @ [V | 1], 5 n-groups (g=4 is the ones column) ----
        {
            uint32_t bf[2][4];
            ldsm4t(vsb[cur], bf[0]);
#pragma unroll
            for (int i = 0; i < 20; i++) {
                const int s = i / 5, g = i % 5;
                if (i + 1 < 20) {
                    const int s2 = (i + 1) / 5, g2 = (i + 1) % 5;
                    ldsm4t(vsb[cur] + (uint32_t)((16 * s2 * KLD + 16 * g2) * 2),
                           bf[(i + 1) & 1]);
                }
                if (g < 4) {
                    mma16(O[0][2 * g],     pf[0][s], bf[i & 1]);
                    mma16(O[0][2 * g + 1], pf[0][s], bf[i & 1] + 2);
                    mma16(O[1][2 * g],     pf[1][s], bf[i & 1]);
                    mma16(O[1][2 * g + 1], pf[1][s], bf[i & 1] + 2);
                } else {
                    mma16(Osum[0], pf[0][s], bf[i & 1]);
                    mma16(Osum[1], pf[1][s], bf[i & 1]);
                }
            }
        }
        __syncthreads();
    }

    // ---- Epilogue: l lives in Osum col 64 (lanes with lane&3==0) ----
#pragma unroll
    for (int t = 0; t < 2; t++) {
        const float l0 = __shfl_sync(0xffffffffu, Osum[t][0], lane & 28);
        const float l1 = __shfl_sync(0xffffffffu, Osum[t][2], lane & 28);
        const float i0 = 1.f / l0, i1 = 1.f / l1;
        __half* Op = AO + ((size_t)b * Ss + q0 + 32 * wp + 16 * t + (lane >> 2)) * Dd
                   + h * DHh + pcol;
#pragma unroll
        for (int j = 0; j < 8; j++) {
            *(__half2*)(Op + 8 * j) =
                __floats2half2_rn(O[t][j][0] * i0, O[t][j][1] * i0);
            *(__half2*)(Op + 8 * (size_t)Dd + 8 * j) =
                __floats2half2_rn(O[t][j][2] * i1, O[t][j][3] * i1);
        }
    }
}

// ---------------------------------------------------------------------------
extern "C" void kernel_launch(void* const* d_in, const int* in_sizes, int n_in,
                              void* d_out, int out_size)
{
    (void)in_sizes; (void)n_in; (void)out_size;
    const float* seq  = (const float*)d_in[0];
    const float* mask = (const float*)d_in[1];
    const float* Wq   = (const float*)d_in[2];
    const float* bq   = (const float*)d_in[3];
    const float* Wk   = (const float*)d_in[4];
    const float* bk   = (const float*)d_in[5];
    const float* Wv   = (const float*)d_in[6];
    const float* bv   = (const float*)d_in[7];
    const float* Wo   = (const float*)d_in[8];
    const float* bo   = (const float*)d_in[9];
    float* out = (float*)d_out;

    __half *Qg, *Kg, *Vg, *AOg, *Xg, *Mg, *Wg;
    cudaGetSymbolAddress((void**)&Qg,  g_Q);
    cudaGetSymbolAddress((void**)&Kg,  g_K);
    cudaGetSymbolAddress((void**)&Vg,  g_V);
    cudaGetSymbolAddress((void**)&AOg, g_AO);
    cudaGetSymbolAddress((void**)&Xg,  g_X);
    cudaGetSymbolAddress((void**)&Mg,  g_maskh);
    cudaGetSymbolAddress((void**)&Wg,  g_Wh);

    cudaFuncSetAttribute(gemm_qkv,
                         cudaFuncAttributeMaxDynamicSharedMemorySize, GEMM_DSMEM);
    cudaFuncSetAttribute(gemm_out,
                         cudaFuncAttributeMaxDynamicSharedMemorySize, GEMM_DSMEM);

    const size_t WSZ = (size_t)Dd * Dd;

    // fp32 -> fp16 conversions
    cvt_f2h<<<4096, 256>>>((const float4*)seq,  (__half2*)Xg,
                           (int)((size_t)Bb * Ss * Dd / 4));
    cvt_f2h<<<8192, 256>>>((const float4*)mask, (__half2*)Mg,
                           (int)((size_t)Ss * Ss / 4));
    cvt_w4<<<dim3(144, 4), 256>>>((const float4*)Wq, (const float4*)Wk,
                                  (const float4*)Wv, (const float4*)Wo,
                                  (__half2*)Wg, (int)(WSZ / 4));

    // QKV projections (alpha_q = SCALE*log2e folded in)
    gemm_qkv<<<dim3(18, (Bb * Ss) / 128), 256, GEMM_DSMEM>>>(
        Xg, bq, bk, bv, Qg, Kg, Vg);

    // Flash attention: grid (bh, q_tile) for mask L2 locality; 4 CTAs/SM
    flash_f16<<<dim3(Bb * Hh, Ss / 128), 128>>>(Qg, Kg, Vg, Mg, AOg);

    // Output projection
    gemm_out<<<dim3(Dd / 128, (Bb * Ss) / 128), 256, GEMM_DSMEM>>>(AOg, bo, out);
}

// round 10
// speedup vs baseline: 1.4824x; 1.4824x over previous
#include <cuda_runtime.h>
#include <cuda_fp16.h>
#include <stdint.h>
#include <math.h>

// Problem constants
#define Bb  2
#define Ss  4096
#define Dd  768
#define Hh  12
#define DHh 64

#define LOG2E 1.44269504088896341f

// Scratch (device globals)
__device__ __half g_Q[(size_t)Bb * Hh * Ss * DHh];
__device__ __half g_K[(size_t)Bb * Hh * Ss * DHh];
__device__ __half g_V[(size_t)Bb * Hh * Ss * DHh];
__device__ __half g_AO[(size_t)Bb * Ss * Dd];
__device__ __half g_X[(size_t)Bb * Ss * Dd];          // seq in half
__device__ __half g_Wh[4][(size_t)Dd * Dd];           // Wq,Wk,Wv,Wo in half
__device__ __half g_maskh[(size_t)Ss * Ss];           // mask in half

// ---------------------------------------------------------------------------
__device__ __forceinline__ uint32_t sptr(const void* p) {
    return (uint32_t)__cvta_generic_to_shared(p);
}
__device__ __forceinline__ void ldsm4(uint32_t a, uint32_t* r) {
    asm volatile("ldmatrix.sync.aligned.m8n8.x4.shared.b16 {%0,%1,%2,%3}, [%4];"
                 : "=r"(r[0]), "=r"(r[1]), "=r"(r[2]), "=r"(r[3]) : "r"(a));
}
__device__ __forceinline__ void ldsm4t(uint32_t a, uint32_t* r) {
    asm volatile("ldmatrix.sync.aligned.m8n8.x4.trans.shared.b16 {%0,%1,%2,%3}, [%4];"
                 : "=r"(r[0]), "=r"(r[1]), "=r"(r[2]), "=r"(r[3]) : "r"(a));
}
__device__ __forceinline__ void mma16(float* d, const uint32_t* a, const uint32_t* b) {
    asm volatile("mma.sync.aligned.m16n8k16.row.col.f32.f16.f16.f32 "
                 "{%0,%1,%2,%3}, {%4,%5,%6,%7}, {%8,%9}, {%0,%1,%2,%3};"
                 : "+f"(d[0]), "+f"(d[1]), "+f"(d[2]), "+f"(d[3])
                 : "r"(a[0]), "r"(a[1]), "r"(a[2]), "r"(a[3]),
                   "r"(b[0]), "r"(b[1]));
}
__device__ __forceinline__ uint32_t pack2(float x, float y) {
    __half2 h = __floats2half2_rn(x, y);
    return *(uint32_t*)&h;
}
__device__ __forceinline__ uint32_t h2exp2(uint32_t x) {
    uint32_t r;
    asm("ex2.approx.f16x2 %0, %1;" : "=r"(r) : "r"(x));
    return r;
}
__device__ __forceinline__ void cp16(uint32_t s, const void* g) {
    asm volatile("cp.async.cg.shared.global [%0], [%1], 16;" :: "r"(s), "l"(g));
}
#define CP_COMMIT() asm volatile("cp.async.commit_group;")
#define CP_WAIT1()  asm volatile("cp.async.wait_group 1;")

// ---------------------------------------------------------------------------
// fp32 -> fp16 conversions
// ---------------------------------------------------------------------------
__global__ void cvt_f2h(const float4* __restrict__ in, __half2* __restrict__ out,
                        int n4)
{
    for (int i = blockIdx.x * blockDim.x + threadIdx.x; i < n4;
         i += gridDim.x * blockDim.x) {
        float4 v = in[i];
        out[2 * i]     = __floats2half2_rn(v.x, v.y);
        out[2 * i + 1] = __floats2half2_rn(v.z, v.w);
    }
}
__global__ void cvt_w4(const float4* __restrict__ w0, const float4* __restrict__ w1,
                       const float4* __restrict__ w2, const float4* __restrict__ w3,
                       __half2* __restrict__ out, int n4)
{
    const float4* src = (blockIdx.y == 0) ? w0 : (blockIdx.y == 1) ? w1
                       : (blockIdx.y == 2) ? w2 : w3;
    __half2* dst = out + (size_t)blockIdx.y * n4 * 2;
    for (int i = blockIdx.x * blockDim.x + threadIdx.x; i < n4;
         i += gridDim.x * blockDim.x) {
        float4 v = src[i];
        dst[2 * i]     = __floats2half2_rn(v.x, v.y);
        dst[2 * i + 1] = __floats2half2_rn(v.z, v.w);
    }
}

// ---------------------------------------------------------------------------
// fp16 GEMM, pure cp.async staging (unchanged, proven)
// ---------------------------------------------------------------------------
#define GKLD 72
#define GSZ (128 * GKLD)
#define GEMM_DSMEM (2 * 2 * GSZ * 2)
#define GNK (Dd / 64)

__device__ __forceinline__ void gemm_body(
    const __half* __restrict__ X, const __half* __restrict__ W,
    const float* __restrict__ bias,
    float* __restrict__ outf, __half* __restrict__ outh,
    float alpha, int mode, int m0, int n0, __half* dsm)
{
    const int tid = threadIdx.x, lane = tid & 31, wp = tid >> 5;
    const int wm = (wp >> 2) * 64, wn = (wp & 3) * 32;

    int row[4], col[4];
#pragma unroll
    for (int c = 0; c < 4; c++) {
        int idx = c * 256 + tid;
        row[c] = idx >> 3; col[c] = (idx & 7) * 8;
    }
    const __half* Xg = X + (size_t)m0 * Dd;
    const __half* Wg = W + (size_t)n0 * Dd;

    uint32_t adst[2][4], bdst[2][4];
#pragma unroll
    for (int st = 0; st < 2; st++)
#pragma unroll
        for (int c = 0; c < 4; c++) {
            adst[st][c] = sptr(dsm + st * 2 * GSZ + row[c] * GKLD + col[c]);
            bdst[st][c] = sptr(dsm + st * 2 * GSZ + GSZ + row[c] * GKLD + col[c]);
        }

    float acc[4][4][4];
#pragma unroll
    for (int i = 0; i < 4; i++)
#pragma unroll
        for (int j = 0; j < 4; j++)
#pragma unroll
            for (int r = 0; r < 4; r++) acc[i][j][r] = 0.f;

    const int arow = wm + (lane & 15);
    const int acol = (lane & 16) ? 8 : 0;
    const int brow = wn + (lane & 7) + ((lane & 16) ? 8 : 0);
    const int bcol = (lane & 8) ? 8 : 0;
    uint32_t xsb[2], wsb[2];
#pragma unroll
    for (int st = 0; st < 2; st++) {
        xsb[st] = sptr(dsm + st * 2 * GSZ) + (uint32_t)((arow * GKLD + acol) * 2);
        wsb[st] = sptr(dsm + st * 2 * GSZ + GSZ) + (uint32_t)((brow * GKLD + bcol) * 2);
    }

#pragma unroll
    for (int c = 0; c < 4; c++) {
        cp16(adst[0][c], Xg + (size_t)row[c] * Dd + col[c]);
        cp16(bdst[0][c], Wg + (size_t)row[c] * Dd + col[c]);
    }
    CP_COMMIT();

    for (int step = 0; step < GNK; step++) {
        const int cur = step & 1;
        if (step + 1 < GNK) {
            const int k0 = (step + 1) * 64;
#pragma unroll
            for (int c = 0; c < 4; c++) {
                cp16(adst[cur ^ 1][c], Xg + (size_t)row[c] * Dd + k0 + col[c]);
                cp16(bdst[cur ^ 1][c], Wg + (size_t)row[c] * Dd + k0 + col[c]);
            }
        }
        CP_COMMIT();
        CP_WAIT1();
        __syncthreads();

#pragma unroll
        for (int s = 0; s < 4; s++) {
            uint32_t af[4][4];
#pragma unroll
            for (int i = 0; i < 4; i++)
                ldsm4(xsb[cur] + (uint32_t)((16 * i * GKLD + 16 * s) * 2), af[i]);
#pragma unroll
            for (int g = 0; g < 2; g++) {
                uint32_t bf[4];
                ldsm4(wsb[cur] + (uint32_t)((16 * g * GKLD + 16 * s) * 2), bf);
#pragma unroll
                for (int i = 0; i < 4; i++) {
                    mma16(acc[i][2 * g],     af[i], bf);
                    mma16(acc[i][2 * g + 1], af[i], bf + 2);
                }
            }
        }
        __syncthreads();
    }

    const int mr = m0 + wm + (lane >> 2);
    const int nc = n0 + wn + 2 * (lane & 3);
#pragma unroll
    for (int j = 0; j < 4; j++) {
        const int n = nc + 8 * j;
        const float bv0 = bias[n], bv1 = bias[n + 1];
#pragma unroll
        for (int i = 0; i < 4; i++) {
            const int m = mr + 16 * i;
            const float r00 = alpha * (acc[i][j][0] + bv0);
            const float r01 = alpha * (acc[i][j][1] + bv1);
            const float r10 = alpha * (acc[i][j][2] + bv0);
            const float r11 = alpha * (acc[i][j][3] + bv1);
            if (mode == 0) {
                const int bb = m >> 12, ss = m & 4095, hh = n >> 6, dh = n & 63;
                __half* p = outh + ((size_t)(bb * Hh + hh) * Ss + ss) * DHh + dh;
                *(__half2*)p = __floats2half2_rn(r00, r01);
                *(__half2*)(p + 8 * DHh) = __floats2half2_rn(r10, r11);
            } else {
                float* p = outf + (size_t)m * Dd + n;
                *(float2*)p = make_float2(r00, r01);
                *(float2*)(p + 8 * Dd) = make_float2(r10, r11);
            }
        }
    }
}

__global__ void __launch_bounds__(256, 2) gemm_qkv(
    const __half* __restrict__ X,
    const float* __restrict__ bq, const float* __restrict__ bk,
    const float* __restrict__ bv,
    __half* __restrict__ Qo, __half* __restrict__ Ko, __half* __restrict__ Vo)
{
    extern __shared__ __half dsm[];
    const int sel = blockIdx.x / 6;
    const int n0 = (blockIdx.x % 6) * 128;
    const int m0 = blockIdx.y * 128;
    const __half* W = g_Wh[sel];
    const float* bias = (sel == 0) ? bq : (sel == 1) ? bk : bv;
    __half* out = (sel == 0) ? Qo : (sel == 1) ? Ko : Vo;
    const float alpha = (sel == 0) ? 0.125f * LOG2E : 1.0f;
    gemm_body(X, W, bias, nullptr, out, alpha, 0, m0, n0, dsm);
}

__global__ void __launch_bounds__(256, 2) gemm_out(
    const __half* __restrict__ X, const float* __restrict__ bias,
    float* __restrict__ out)
{
    extern __shared__ __half dsm[];
    gemm_body(X, g_Wh[3], bias, out, nullptr, 1.0f, 1,
              blockIdx.y * 128, blockIdx.x * 128, dsm);
}

// ---------------------------------------------------------------------------
// fp16 flash attention: FA2 layout (4 warps x 32 Q rows), 3 CTAs/SM.
// grid (q_tile, bh): consecutive CTAs share the same head's K/V in L2 (R8
// layout, proven). cp.async double-buffered K/V; half2 approx exp;
// row sums via ones-column MMA (V tile KLD=88, col 64 = 1.0).
// ---------------------------------------------------------------------------
#define KLD 88
#define TILE_H (64 * KLD)

__global__ void __launch_bounds__(128, 3) flash_f16(
    const __half* __restrict__ Q, const __half* __restrict__ K,
    const __half* __restrict__ V, const __half* __restrict__ mask,
    __half* __restrict__ AO)
{
    __shared__ __half sm[2][2][TILE_H];

    const int tid = threadIdx.x, lane = tid & 31, wp = tid >> 5;
    const int q0 = blockIdx.x * 128;            // R8 grid order restored
    const int bh = blockIdx.y;
    const int b = bh / Hh, h = bh - b * Hh;

    const __half* Qp = Q + ((size_t)bh * Ss + q0) * DHh;
    const __half* Kp = K + (size_t)bh * Ss * DHh;
    const __half* Vp = V + (size_t)bh * Ss * DHh;

    // ---- Stage Q tile, load A-frags ----
    {
        __half* qstage = &sm[0][0][0];
#pragma unroll
        for (int c = 0; c < 8; c++) {
            int idx = c * 128 + tid;
            int r = idx >> 3, ch = (idx & 7) * 8;
            *(uint4*)&qstage[r * KLD + ch] = *(const uint4*)(Qp + (size_t)r * DHh + ch);
        }
    }
    __syncthreads();

    uint32_t qf[2][4][4];
#pragma unroll
    for (int t = 0; t < 2; t++) {
        const uint32_t qb = sptr(&sm[0][0][0]) +
            (uint32_t)(((32 * wp + 16 * t + (lane & 15)) * KLD +
                        ((lane & 16) ? 8 : 0)) * 2);
#pragma unroll
        for (int s = 0; s < 4; s++) ldsm4(qb + (uint32_t)(16 * s * 2), qf[t][s]);
    }
    __syncthreads();

    // ---- Init ones-column region of V buffers (cols 64..79, both stages) ----
    {
        const int st = tid >> 6, r = tid & 63;
        __half2* p = (__half2*)&sm[st][1][r * KLD + 64];
        p[0] = __floats2half2_rn(1.f, 0.f);
#pragma unroll
        for (int j = 1; j < 8; j++) p[j] = __floats2half2_rn(0.f, 0.f);
    }

    int srow[4], scol[4];
#pragma unroll
    for (int c = 0; c < 4; c++) {
        int idx = c * 128 + tid;
        srow[c] = idx >> 3; scol[c] = (idx & 7) * 8;
    }
    uint32_t kdst[2][4], vdst[2][4];
#pragma unroll
    for (int st = 0; st < 2; st++)
#pragma unroll
        for (int c = 0; c < 4; c++) {
            kdst[st][c] = sptr(&sm[st][0][srow[c] * KLD + scol[c]]);
            vdst[st][c] = sptr(&sm[st][1][srow[c] * KLD + scol[c]]);
        }

    const int krow = (lane & 7) + ((lane & 16) ? 8 : 0);
    const int kcol = (lane & 8) ? 8 : 0;
    const int vrow = lane & 15;
    const int vcol = (lane & 16) ? 8 : 0;
    uint32_t ksb[2], vsb[2];
#pragma unroll
    for (int st = 0; st < 2; st++) {
        ksb[st] = sptr(&sm[st][0][0]) + (uint32_t)((krow * KLD + kcol) * 2);
        vsb[st] = sptr(&sm[st][1][0]) + (uint32_t)((vrow * KLD + vcol) * 2);
    }

    float O[2][8][4];
    float Osum[2][4];
#pragma unroll
    for (int t = 0; t < 2; t++) {
#pragma unroll
        for (int j = 0; j < 8; j++)
#pragma unroll
            for (int r = 0; r < 4; r++) O[t][j][r] = 0.f;
#pragma unroll
        for (int r = 0; r < 4; r++) Osum[t][r] = 0.f;
    }
    float mr[2][2] = {{-1e30f, -1e30f}, {-1e30f, -1e30f}};

    const int pcol = 2 * (lane & 3);
    const __half* mbase[2];
#pragma unroll
    for (int t = 0; t < 2; t++)
        mbase[t] = mask + (size_t)(q0 + 32 * wp + 16 * t + (lane >> 2)) * Ss + pcol;

    const int NT = Ss / 64;

#pragma unroll
    for (int c = 0; c < 4; c++) {
        cp16(kdst[0][c], Kp + (size_t)srow[c] * DHh + scol[c]);
        cp16(vdst[0][c], Vp + (size_t)srow[c] * DHh + scol[c]);
    }
    CP_COMMIT();

    for (int kt = 0; kt < NT; kt++) {
        const int cur = kt & 1;
        if (kt + 1 < NT) {
            const __half* Kn = Kp + (size_t)(kt + 1) * 64 * DHh;
            const __half* Vn = Vp + (size_t)(kt + 1) * 64 * DHh;
#pragma unroll
            for (int c = 0; c < 4; c++) {
                cp16(kdst[cur ^ 1][c], Kn + (size_t)srow[c] * DHh + scol[c]);
                cp16(vdst[cur ^ 1][c], Vn + (size_t)srow[c] * DHh + scol[c]);
            }
        }
        CP_COMMIT();
        CP_WAIT1();
        __syncthreads();

        // ---- Scores ----
        float sc[2][8][4];
#pragma unroll
        for (int t = 0; t < 2; t++)
#pragma unroll
            for (int j = 0; j < 8; j++)
#pragma unroll
                for (int r = 0; r < 4; r++) sc[t][j][r] = 0.f;

        {
            uint32_t bf[2][4];
            ldsm4(ksb[cur], bf[0]);
#pragma unroll
            for (int i = 0; i < 16; i++) {
                const int s = i >> 2, g = i & 3;
                if (i + 1 < 16) {
                    const int s2 = (i + 1) >> 2, g2 = (i + 1) & 3;
                    ldsm4(ksb[cur] + (uint32_t)((16 * g2 * KLD + 16 * s2) * 2),
                          bf[(i + 1) & 1]);
                }
                mma16(sc[0][2 * g],     qf[0][s], bf[i & 1]);
                mma16(sc[0][2 * g + 1], qf[0][s], bf[i & 1] + 2);
                mma16(sc[1][2 * g],     qf[1][s], bf[i & 1]);
                mma16(sc[1][2 * g + 1], qf[1][s], bf[i & 1] + 2);
            }
        }

        // ---- Mask + online softmax (half2 approx exp; sums via PV MMA) ----
        uint32_t pf[2][4][4];
#pragma unroll
        for (int t = 0; t < 2; t++) {
            const __half* mp = mbase[t] + kt * 64;
#pragma unroll
            for (int j = 0; j < 8; j++) {
                float2 m0v = __half22float2(*(const __half2*)(mp + 8 * j));
                float2 m1v = __half22float2(*(const __half2*)(mp + 8 * (size_t)Ss + 8 * j));
                sc[t][j][0] = fmaf(m0v.x, LOG2E, sc[t][j][0]);
                sc[t][j][1] = fmaf(m0v.y, LOG2E, sc[t][j][1]);
                sc[t][j][2] = fmaf(m1v.x, LOG2E, sc[t][j][2]);
                sc[t][j][3] = fmaf(m1v.y, LOG2E, sc[t][j][3]);
            }

            float mx0 = -1e30f, mx1 = -1e30f;
#pragma unroll
            for (int j = 0; j < 8; j++) {
                mx0 = fmaxf(mx0, fmaxf(sc[t][j][0], sc[t][j][1]));
                mx1 = fmaxf(mx1, fmaxf(sc[t][j][2], sc[t][j][3]));
            }
            mx0 = fmaxf(mx0, __shfl_xor_sync(0xffffffffu, mx0, 1));
            mx0 = fmaxf(mx0, __shfl_xor_sync(0xffffffffu, mx0, 2));
            mx1 = fmaxf(mx1, __shfl_xor_sync(0xffffffffu, mx1, 1));
            mx1 = fmaxf(mx1, __shfl_xor_sync(0xffffffffu, mx1, 2));
            const float mn0 = fmaxf(mr[t][0], mx0), mn1 = fmaxf(mr[t][1], mx1);
            const float s0 = exp2f(mr[t][0] - mn0), s1 = exp2f(mr[t][1] - mn1);
            mr[t][0] = mn0; mr[t][1] = mn1;

#pragma unroll
            for (int s = 0; s < 4; s++) {
                pf[t][s][0] = h2exp2(pack2(sc[t][2 * s][0] - mn0,
                                           sc[t][2 * s][1] - mn0));
                pf[t][s][1] = h2exp2(pack2(sc[t][2 * s][2] - mn1,
                                           sc[t][2 * s][3] - mn1));
                pf[t][s][2] = h2exp2(pack2(sc[t][2 * s + 1][0] - mn0,
                                           sc[t][2 * s + 1][1] - mn0));
                pf[t][s][3] = h2exp2(pack2(sc[t][2 * s + 1][2] - mn1,
                                           sc[t][2 * s + 1][3] - mn1));
            }

#pragma unroll
            for (int j = 0; j < 8; j++) {
                O[t][j][0] *= s0; O[t][j][1] *= s0;
                O[t][j][2] *= s1; O[t][j][3] *= s1;
            }
            Osum[t][0] *= s0; Osum[t][1] *= s0;
            Osum[t][2] *= s1; Osum[t][3] *= s1;
        }

        // ---- O += P @ [V | 1], 5 n-groups (g=4 is the ones column) ----
        {
            uint32_t bf[2][4];
            ldsm4t(vsb[cur], bf[0]);
#pragma unroll
            for (int i = 0; i < 20; i++) {
                const int s = i / 5, g = i % 5;
                if (i + 1 < 20) {
                    const int s2 = (i + 1) / 5, g2 = (i + 1) % 5;
                    ldsm4t(vsb[cur] + (uint32_t)((16 * s2 * KLD + 16 * g2) * 2),
                           bf[(i + 1) & 1]);
                }
                if (g < 4) {
                    mma16(O[0][2 * g],     pf[0][s], bf[i & 1]);
                    mma16(O[0][2 * g + 1], pf[0][s], bf[i & 1] + 2);
                    mma16(O[1][2 * g],     pf[1][s], bf[i & 1]);
                    mma16(O[1][2 * g + 1], pf[1][s], bf[i & 1] + 2);
                } else {
                    mma16(Osum[0], pf[0][s], bf[i & 1]);
                    mma16(Osum[1], pf[1][s], bf[i & 1]);
                }
            }
        }
        __syncthreads();
    }

    // ---- Epilogue: l lives in Osum col 64 (lanes with lane&3==0) ----
#pragma unroll
    for (int t = 0; t < 2; t++) {
        const float l0 = __shfl_sync(0xffffffffu, Osum[t][0], lane & 28);
        const float l1 = __shfl_sync(0xffffffffu, Osum[t][2], lane & 28);
        const float i0 = 1.f / l0, i1 = 1.f / l1;
        __half* Op = AO + ((size_t)b * Ss + q0 + 32 * wp + 16 * t + (lane >> 2)) * Dd
                   + h * DHh + pcol;
#pragma unroll
        for (int j = 0; j < 8; j++) {
            *(__half2*)(Op + 8 * j) =
                __floats2half2_rn(O[t][j][0] * i0, O[t][j][1] * i0);
            *(__half2*)(Op + 8 * (size_t)Dd + 8 * j) =
                __floats2half2_rn(O[t][j][2] * i1, O[t][j][3] * i1);
        }
    }
}

// ---------------------------------------------------------------------------
extern "C" void kernel_launch(void* const* d_in, const int* in_sizes, int n_in,
                              void* d_out, int out_size)
{
    (void)in_sizes; (void)n_in; (void)out_size;
    const float* seq  = (const float*)d_in[0];
    const float* mask = (const float*)d_in[1];
    const float* Wq   = (const float*)d_in[2];
    const float* bq   = (const float*)d_in[3];
    const float* Wk   = (const float*)d_in[4];
    const float* bk   = (const float*)d_in[5];
    const float* Wv   = (const float*)d_in[6];
    const float* bv   = (const float*)d_in[7];
    const float* Wo   = (const float*)d_in[8];
    const float* bo   = (const float*)d_in[9];
    float* out = (float*)d_out;

    __half *Qg, *Kg, *Vg, *AOg, *Xg, *Mg, *Wg;
    cudaGetSymbolAddress((void**)&Qg,  g_Q);
    cudaGetSymbolAddress((void**)&Kg,  g_K);
    cudaGetSymbolAddress((void**)&Vg,  g_V);
    cudaGetSymbolAddress((void**)&AOg, g_AO);
    cudaGetSymbolAddress((void**)&Xg,  g_X);
    cudaGetSymbolAddress((void**)&Mg,  g_maskh);
    cudaGetSymbolAddress((void**)&Wg,  g_Wh);

    cudaFuncSetAttribute(gemm_qkv,
                         cudaFuncAttributeMaxDynamicSharedMemorySize, GEMM_DSMEM);
    cudaFuncSetAttribute(gemm_out,
                         cudaFuncAttributeMaxDynamicSharedMemorySize, GEMM_DSMEM);

    const size_t WSZ = (size_t)Dd * Dd;

    // fp32 -> fp16 conversions
    cvt_f2h<<<4096, 256>>>((const float4*)seq,  (__half2*)Xg,
                           (int)((size_t)Bb * Ss * Dd / 4));
    cvt_f2h<<<8192, 256>>>((const float4*)mask, (__half2*)Mg,
                           (int)((size_t)Ss * Ss / 4));
    cvt_w4<<<dim3(144, 4), 256>>>((const float4*)Wq, (const float4*)Wk,
                                  (const float4*)Wv, (const float4*)Wo,
                                  (__half2*)Wg, (int)(WSZ / 4));

    // QKV projections (alpha_q = SCALE*log2e folded in)
    gemm_qkv<<<dim3(18, (Bb * Ss) / 128), 256, GEMM_DSMEM>>>(
        Xg, bq, bk, bv, Qg, Kg, Vg);

    // Flash attention: R8 grid order (q_tile, bh) restored; 3 CTAs/SM
    flash_f16<<<dim3(Ss / 128, Bb * Hh), 128>>>(Qg, Kg, Vg, Mg, AOg);

    // Output projection
    gemm_out<<<dim3(Dd / 128, (Bb * Ss) / 128), 256, GEMM_DSMEM>>>(AOg, bo, out);
}

// round 11
// speedup vs baseline: 2.4132x; 1.6280x over previous
#include <cuda_runtime.h>
#include <cuda_fp16.h>
#include <stdint.h>
#include <math.h>

// Problem constants
#define Bb  2
#define Ss  4096
#define Dd  768
#define Hh  12
#define DHh 64

#define LOG2E 1.44269504088896341f

// Scratch (device globals)
__device__ __half g_Q[(size_t)Bb * Hh * Ss * DHh];
__device__ __half g_K[(size_t)Bb * Hh * Ss * DHh];
__device__ __half g_V[(size_t)Bb * Hh * Ss * DHh];
__device__ __half g_AO[(size_t)Bb * Ss * Dd];
__device__ __half g_X[(size_t)Bb * Ss * Dd];          // seq in half
__device__ __half g_Wh[4][(size_t)Dd * Dd];           // Wq,Wk,Wv,Wo in half
__device__ __half g_maskh[(size_t)Ss * Ss];           // mask in half
__device__ int    g_mflag;                            // 1 if any mask bit nonzero

// ---------------------------------------------------------------------------
__device__ __forceinline__ uint32_t sptr(const void* p) {
    return (uint32_t)__cvta_generic_to_shared(p);
}
__device__ __forceinline__ void ldsm4(uint32_t a, uint32_t* r) {
    asm volatile("ldmatrix.sync.aligned.m8n8.x4.shared.b16 {%0,%1,%2,%3}, [%4];"
                 : "=r"(r[0]), "=r"(r[1]), "=r"(r[2]), "=r"(r[3]) : "r"(a));
}
__device__ __forceinline__ void ldsm4t(uint32_t a, uint32_t* r) {
    asm volatile("ldmatrix.sync.aligned.m8n8.x4.trans.shared.b16 {%0,%1,%2,%3}, [%4];"
                 : "=r"(r[0]), "=r"(r[1]), "=r"(r[2]), "=r"(r[3]) : "r"(a));
}
__device__ __forceinline__ void mma16(float* d, const uint32_t* a, const uint32_t* b) {
    asm volatile("mma.sync.aligned.m16n8k16.row.col.f32.f16.f16.f32 "
                 "{%0,%1,%2,%3}, {%4,%5,%6,%7}, {%8,%9}, {%0,%1,%2,%3};"
                 : "+f"(d[0]), "+f"(d[1]), "+f"(d[2]), "+f"(d[3])
                 : "r"(a[0]), "r"(a[1]), "r"(a[2]), "r"(a[3]),
                   "r"(b[0]), "r"(b[1]));
}
__device__ __forceinline__ uint32_t pack2(float x, float y) {
    __half2 h = __floats2half2_rn(x, y);
    return *(uint32_t*)&h;
}
__device__ __forceinline__ uint32_t h2exp2(uint32_t x) {
    uint32_t r;
    asm("ex2.approx.f16x2 %0, %1;" : "=r"(r) : "r"(x));
    return r;
}
__device__ __forceinline__ void cp16(uint32_t s, const void* g) {
    asm volatile("cp.async.cg.shared.global [%0], [%1], 16;" :: "r"(s), "l"(g));
}
#define CP_COMMIT() asm volatile("cp.async.commit_group;")
#define CP_WAIT1()  asm volatile("cp.async.wait_group 1;")

// ---------------------------------------------------------------------------
// fp32 -> fp16 conversions
// ---------------------------------------------------------------------------
__global__ void cvt_f2h(const float4* __restrict__ in, __half2* __restrict__ out,
                        int n4)
{
    for (int i = blockIdx.x * blockDim.x + threadIdx.x; i < n4;
         i += gridDim.x * blockDim.x) {
        float4 v = in[i];
        out[2 * i]     = __floats2half2_rn(v.x, v.y);
        out[2 * i + 1] = __floats2half2_rn(v.z, v.w);
    }
}
// mask conversion fused with nonzero detection (block OR -> atomicOr)
__global__ void cvt_mask(const float4* __restrict__ in, __half2* __restrict__ out,
                         int n4)
{
    uint32_t nz = 0;
    for (int i = blockIdx.x * blockDim.x + threadIdx.x; i < n4;
         i += gridDim.x * blockDim.x) {
        float4 v = in[i];
        nz |= __float_as_uint(v.x) | __float_as_uint(v.y) |
              __float_as_uint(v.z) | __float_as_uint(v.w);
        out[2 * i]     = __floats2half2_rn(v.x, v.y);
        out[2 * i + 1] = __floats2half2_rn(v.z, v.w);
    }
    nz = __syncthreads_or(nz != 0u);
    if (threadIdx.x == 0 && nz) atomicOr(&g_mflag, 1);
}
__global__ void cvt_w4(const float4* __restrict__ w0, const float4* __restrict__ w1,
                       const float4* __restrict__ w2, const float4* __restrict__ w3,
                       __half2* __restrict__ out, int n4)
{
    const float4* src = (blockIdx.y == 0) ? w0 : (blockIdx.y == 1) ? w1
                       : (blockIdx.y == 2) ? w2 : w3;
    __half2* dst = out + (size_t)blockIdx.y * n4 * 2;
    for (int i = blockIdx.x * blockDim.x + threadIdx.x; i < n4;
         i += gridDim.x * blockDim.x) {
        float4 v = src[i];
        dst[2 * i]     = __floats2half2_rn(v.x, v.y);
        dst[2 * i + 1] = __floats2half2_rn(v.z, v.w);
    }
}

// ---------------------------------------------------------------------------
// fp16 GEMM, pure cp.async staging (unchanged, proven)
// ---------------------------------------------------------------------------
#define GKLD 72
#define GSZ (128 * GKLD)
#define GEMM_DSMEM (2 * 2 * GSZ * 2)
#define GNK (Dd / 64)

__device__ __forceinline__ void gemm_body(
    const __half* __restrict__ X, const __half* __restrict__ W,
    const float* __restrict__ bias,
    float* __restrict__ outf, __half* __restrict__ outh,
    float alpha, int mode, int m0, int n0, __half* dsm)
{
    const int tid = threadIdx.x, lane = tid & 31, wp = tid >> 5;
    const int wm = (wp >> 2) * 64, wn = (wp & 3) * 32;

    int row[4], col[4];
#pragma unroll
    for (int c = 0; c < 4; c++) {
        int idx = c * 256 + tid;
        row[c] = idx >> 3; col[c] = (idx & 7) * 8;
    }
    const __half* Xg = X + (size_t)m0 * Dd;
    const __half* Wg = W + (size_t)n0 * Dd;

    uint32_t adst[2][4], bdst[2][4];
#pragma unroll
    for (int st = 0; st < 2; st++)
#pragma unroll
        for (int c = 0; c < 4; c++) {
            adst[st][c] = sptr(dsm + st * 2 * GSZ + row[c] * GKLD + col[c]);
            bdst[st][c] = sptr(dsm + st * 2 * GSZ + GSZ + row[c] * GKLD + col[c]);
        }

    float acc[4][4][4];
#pragma unroll
    for (int i = 0; i < 4; i++)
#pragma unroll
        for (int j = 0; j < 4; j++)
#pragma unroll
            for (int r = 0; r < 4; r++) acc[i][j][r] = 0.f;

    const int arow = wm + (lane & 15);
    const int acol = (lane & 16) ? 8 : 0;
    const int brow = wn + (lane & 7) + ((lane & 16) ? 8 : 0);
    const int bcol = (lane & 8) ? 8 : 0;
    uint32_t xsb[2], wsb[2];
#pragma unroll
    for (int st = 0; st < 2; st++) {
        xsb[st] = sptr(dsm + st * 2 * GSZ) + (uint32_t)((arow * GKLD + acol) * 2);
        wsb[st] = sptr(dsm + st * 2 * GSZ + GSZ) + (uint32_t)((brow * GKLD + bcol) * 2);
    }

#pragma unroll
    for (int c = 0; c < 4; c++) {
        cp16(adst[0][c], Xg + (size_t)row[c] * Dd + col[c]);
        cp16(bdst[0][c], Wg + (size_t)row[c] * Dd + col[c]);
    }
    CP_COMMIT();

    for (int step = 0; step < GNK; step++) {
        const int cur = step & 1;
        if (step + 1 < GNK) {
            const int k0 = (step + 1) * 64;
#pragma unroll
            for (int c = 0; c < 4; c++) {
                cp16(adst[cur ^ 1][c], Xg + (size_t)row[c] * Dd + k0 + col[c]);
                cp16(bdst[cur ^ 1][c], Wg + (size_t)row[c] * Dd + k0 + col[c]);
            }
        }
        CP_COMMIT();
        CP_WAIT1();
        __syncthreads();

#pragma unroll
        for (int s = 0; s < 4; s++) {
            uint32_t af[4][4];
#pragma unroll
            for (int i = 0; i < 4; i++)
                ldsm4(xsb[cur] + (uint32_t)((16 * i * GKLD + 16 * s) * 2), af[i]);
#pragma unroll
            for (int g = 0; g < 2; g++) {
                uint32_t bf[4];
                ldsm4(wsb[cur] + (uint32_t)((16 * g * GKLD + 16 * s) * 2), bf);
#pragma unroll
                for (int i = 0; i < 4; i++) {
                    mma16(acc[i][2 * g],     af[i], bf);
                    mma16(acc[i][2 * g + 1], af[i], bf + 2);
                }
            }
        }
        __syncthreads();
    }

    const int mr = m0 + wm + (lane >> 2);
    const int nc = n0 + wn + 2 * (lane & 3);
#pragma unroll
    for (int j = 0; j < 4; j++) {
        const int n = nc + 8 * j;
        const float bv0 = bias[n], bv1 = bias[n + 1];
#pragma unroll
        for (int i = 0; i < 4; i++) {
            const int m = mr + 16 * i;
            const float r00 = alpha * (acc[i][j][0] + bv0);
            const float r01 = alpha * (acc[i][j][1] + bv1);
            const float r10 = alpha * (acc[i][j][2] + bv0);
            const float r11 = alpha * (acc[i][j][3] + bv1);
            if (mode == 0) {
                const int bb = m >> 12, ss = m & 4095, hh = n >> 6, dh = n & 63;
                __half* p = outh + ((size_t)(bb * Hh + hh) * Ss + ss) * DHh + dh;
                *(__half2*)p = __floats2half2_rn(r00, r01);
                *(__half2*)(p + 8 * DHh) = __floats2half2_rn(r10, r11);
            } else {
                float* p = outf + (size_t)m * Dd + n;
                *(float2*)p = make_float2(r00, r01);
                *(float2*)(p + 8 * Dd) = make_float2(r10, r11);
            }
        }
    }
}

__global__ void __launch_bounds__(256, 2) gemm_qkv(
    const __half* __restrict__ X,
    const float* __restrict__ bq, const float* __restrict__ bk,
    const float* __restrict__ bv,
    __half* __restrict__ Qo, __half* __restrict__ Ko, __half* __restrict__ Vo)
{
    extern __shared__ __half dsm[];
    const int sel = blockIdx.x / 6;
    const int n0 = (blockIdx.x % 6) * 128;
    const int m0 = blockIdx.y * 128;
    const __half* W = g_Wh[sel];
    const float* bias = (sel == 0) ? bq : (sel == 1) ? bk : bv;
    __half* out = (sel == 0) ? Qo : (sel == 1) ? Ko : Vo;
    const float alpha = (sel == 0) ? 0.125f * LOG2E : 1.0f;
    gemm_body(X, W, bias, nullptr, out, alpha, 0, m0, n0, dsm);
}

__global__ void __launch_bounds__(256, 2) gemm_out(
    const __half* __restrict__ X, const float* __restrict__ bias,
    float* __restrict__ out)
{
    extern __shared__ __half dsm[];
    gemm_body(X, g_Wh[3], bias, out, nullptr, 1.0f, 1,
              blockIdx.y * 128, blockIdx.x * 128, dsm);
}

// ---------------------------------------------------------------------------
// fp16 flash attention: exact R8 configuration (4 warps x 32 Q rows,
// 2 CTAs/SM, grid (q_tile, bh)), plus a zero-mask fast path: when g_mflag==0
// all mask loads/FMAs are skipped (uniform branch; adding 0.0 is the identity,
// so results are bit-identical).
// ---------------------------------------------------------------------------
#define KLD 88
#define TILE_H (64 * KLD)

__global__ void __launch_bounds__(128, 2) flash_f16(
    const __half* __restrict__ Q, const __half* __restrict__ K,
    const __half* __restrict__ V, const __half* __restrict__ mask,
    __half* __restrict__ AO)
{
    __shared__ __half sm[2][2][TILE_H];

    const int tid = threadIdx.x, lane = tid & 31, wp = tid >> 5;
    const int q0 = blockIdx.x * 128;
    const int bh = blockIdx.y;
    const int b = bh / Hh, h = bh - b * Hh;
    const int mf = g_mflag;                    // uniform across grid

    const __half* Qp = Q + ((size_t)bh * Ss + q0) * DHh;
    const __half* Kp = K + (size_t)bh * Ss * DHh;
    const __half* Vp = V + (size_t)bh * Ss * DHh;

    // ---- Stage Q tile, load A-frags ----
    {
        __half* qstage = &sm[0][0][0];
#pragma unroll
        for (int c = 0; c < 8; c++) {
            int idx = c * 128 + tid;
            int r = idx >> 3, ch = (idx & 7) * 8;
            *(uint4*)&qstage[r * KLD + ch] = *(const uint4*)(Qp + (size_t)r * DHh + ch);
        }
    }
    __syncthreads();

    uint32_t qf[2][4][4];
#pragma unroll
    for (int t = 0; t < 2; t++) {
        const uint32_t qb = sptr(&sm[0][0][0]) +
            (uint32_t)(((32 * wp + 16 * t + (lane & 15)) * KLD +
                        ((lane & 16) ? 8 : 0)) * 2);
#pragma unroll
        for (int s = 0; s < 4; s++) ldsm4(qb + (uint32_t)(16 * s * 2), qf[t][s]);
    }
    __syncthreads();

    // ---- Init ones-column region of V buffers (cols 64..79, both stages) ----
    {
        const int st = tid >> 6, r = tid & 63;
        __half2* p = (__half2*)&sm[st][1][r * KLD + 64];
        p[0] = __floats2half2_rn(1.f, 0.f);
#pragma unroll
        for (int j = 1; j < 8; j++) p[j] = __floats2half2_rn(0.f, 0.f);
    }

    int srow[4], scol[4];
#pragma unroll
    for (int c = 0; c < 4; c++) {
        int idx = c * 128 + tid;
        srow[c] = idx >> 3; scol[c] = (idx & 7) * 8;
    }
    uint32_t kdst[2][4], vdst[2][4];
#pragma unroll
    for (int st = 0; st < 2; st++)
#pragma unroll
        for (int c = 0; c < 4; c++) {
            kdst[st][c] = sptr(&sm[st][0][srow[c] * KLD + scol[c]]);
            vdst[st][c] = sptr(&sm[st][1][srow[c] * KLD + scol[c]]);
        }

    const int krow = (lane & 7) + ((lane & 16) ? 8 : 0);
    const int kcol = (lane & 8) ? 8 : 0;
    const int vrow = lane & 15;
    const int vcol = (lane & 16) ? 8 : 0;
    uint32_t ksb[2], vsb[2];
#pragma unroll
    for (int st = 0; st < 2; st++) {
        ksb[st] = sptr(&sm[st][0][0]) + (uint32_t)((krow * KLD + kcol) * 2);
        vsb[st] = sptr(&sm[st][1][0]) + (uint32_t)((vrow * KLD + vcol) * 2);
    }

    float O[2][8][4];
    float Osum[2][4];
#pragma unroll
    for (int t = 0; t < 2; t++) {
#pragma unroll
        for (int j = 0; j < 8; j++)
#pragma unroll
            for (int r = 0; r < 4; r++) O[t][j][r] = 0.f;
#pragma unroll
        for (int r = 0; r < 4; r++) Osum[t][r] = 0.f;
    }
    float mr[2][2] = {{-1e30f, -1e30f}, {-1e30f, -1e30f}};

    const int pcol = 2 * (lane & 3);
    const __half* mbase[2];
#pragma unroll
    for (int t = 0; t < 2; t++)
        mbase[t] = mask + (size_t)(q0 + 32 * wp + 16 * t + (lane >> 2)) * Ss + pcol;

    const int NT = Ss / 64;

#pragma unroll
    for (int c = 0; c < 4; c++) {
        cp16(kdst[0][c], Kp + (size_t)srow[c] * DHh + scol[c]);
        cp16(vdst[0][c], Vp + (size_t)srow[c] * DHh + scol[c]);
    }
    CP_COMMIT();

    for (int kt = 0; kt < NT; kt++) {
        const int cur = kt & 1;
        if (kt + 1 < NT) {
            const __half* Kn = Kp + (size_t)(kt + 1) * 64 * DHh;
            const __half* Vn = Vp + (size_t)(kt + 1) * 64 * DHh;
#pragma unroll
            for (int c = 0; c < 4; c++) {
                cp16(kdst[cur ^ 1][c], Kn + (size_t)srow[c] * DHh + scol[c]);
                cp16(vdst[cur ^ 1][c], Vn + (size_t)srow[c] * DHh + scol[c]);
            }
        }
        CP_COMMIT();
        CP_WAIT1();
        __syncthreads();

        // ---- Scores ----
        float sc[2][8][4];
#pragma unroll
        for (int t = 0; t < 2; t++)
#pragma unroll
            for (int j = 0; j < 8; j++)
#pragma unroll
                for (int r = 0; r < 4; r++) sc[t][j][r] = 0.f;

        {
            uint32_t bf[2][4];
            ldsm4(ksb[cur], bf[0]);
#pragma unroll
            for (int i = 0; i < 16; i++) {
                const int s = i >> 2, g = i & 3;
                if (i + 1 < 16) {
                    const int s2 = (i + 1) >> 2, g2 = (i + 1) & 3;
                    ldsm4(ksb[cur] + (uint32_t)((16 * g2 * KLD + 16 * s2) * 2),
                          bf[(i + 1) & 1]);
                }
                mma16(sc[0][2 * g],     qf[0][s], bf[i & 1]);
                mma16(sc[0][2 * g + 1], qf[0][s], bf[i & 1] + 2);
                mma16(sc[1][2 * g],     qf[1][s], bf[i & 1]);
                mma16(sc[1][2 * g + 1], qf[1][s], bf[i & 1] + 2);
            }
        }

        // ---- Mask (skipped when all-zero) + online softmax ----
        uint32_t pf[2][4][4];
#pragma unroll
        for (int t = 0; t < 2; t++) {
            if (mf) {
                const __half* mp = mbase[t] + kt * 64;
#pragma unroll
                for (int j = 0; j < 8; j++) {
                    float2 m0v = __half22float2(*(const __half2*)(mp + 8 * j));
                    float2 m1v = __half22float2(*(const __half2*)(mp + 8 * (size_t)Ss + 8 * j));
                    sc[t][j][0] = fmaf(m0v.x, LOG2E, sc[t][j][0]);
                    sc[t][j][1] = fmaf(m0v.y, LOG2E, sc[t][j][1]);
                    sc[t][j][2] = fmaf(m1v.x, LOG2E, sc[t][j][2]);
                    sc[t][j][3] = fmaf(m1v.y, LOG2E, sc[t][j][3]);
                }
            }

            float mx0 = -1e30f, mx1 = -1e30f;
#pragma unroll
            for (int j = 0; j < 8; j++) {
                mx0 = fmaxf(mx0, fmaxf(sc[t][j][0], sc[t][j][1]));
                mx1 = fmaxf(mx1, fmaxf(sc[t][j][2], sc[t][j][3]));
            }
            mx0 = fmaxf(mx0, __shfl_xor_sync(0xffffffffu, mx0, 1));
            mx0 = fmaxf(mx0, __shfl_xor_sync(0xffffffffu, mx0, 2));
            mx1 = fmaxf(mx1, __shfl_xor_sync(0xffffffffu, mx1, 1));
            mx1 = fmaxf(mx1, __shfl_xor_sync(0xffffffffu, mx1, 2));
            const float mn0 = fmaxf(mr[t][0], mx0), mn1 = fmaxf(mr[t][1], mx1);
            const float s0 = exp2f(mr[t][0] - mn0), s1 = exp2f(mr[t][1] - mn1);
            mr[t][0] = mn0; mr[t][1] = mn1;

#pragma unroll
            for (int s = 0; s < 4; s++) {
                pf[t][s][0] = h2exp2(pack2(sc[t][2 * s][0] - mn0,
                                           sc[t][2 * s][1] - mn0));
                pf[t][s][1] = h2exp2(pack2(sc[t][2 * s][2] - mn1,
                                           sc[t][2 * s][3] - mn1));
                pf[t][s][2] = h2exp2(pack2(sc[t][2 * s + 1][0] - mn0,
                                           sc[t][2 * s + 1][1] - mn0));
                pf[t][s][3] = h2exp2(pack2(sc[t][2 * s + 1][2] - mn1,
                                           sc[t][2 * s + 1][3] - mn1));
            }

#pragma unroll
            for (int j = 0; j < 8; j++) {
                O[t][j][0] *= s0; O[t][j][1] *= s0;
                O[t][j][2] *= s1; O[t][j][3] *= s1;
            }
            Osum[t][0] *= s0; Osum[t][1] *= s0;
            Osum[t][2] *= s1; Osum[t][3] *= s1;
        }

        // ---- O += P @ [V | 1], 5 n-groups (g=4 is the ones column) ----
        {
            uint32_t bf[2][4];
            ldsm4t(vsb[cur], bf[0]);
#pragma unroll
            for (int i = 0; i < 20; i++) {
                const int s = i / 5, g = i % 5;
                if (i + 1 < 20) {
                    const int s2 = (i + 1) / 5, g2 = (i + 1) % 5;
                    ldsm4t(vsb[cur] + (uint32_t)((16 * s2 * KLD + 16 * g2) * 2),
                           bf[(i + 1) & 1]);
                }
                if (g < 4) {
                    mma16(O[0][2 * g],     pf[0][s], bf[i & 1]);
                    mma16(O[0][2 * g + 1], pf[0][s], bf[i & 1] + 2);
                    mma16(O[1][2 * g],     pf[1][s], bf[i & 1]);
                    mma16(O[1][2 * g + 1], pf[1][s], bf[i & 1] + 2);
                } else {
                    mma16(Osum[0], pf[0][s], bf[i & 1]);
                    mma16(Osum[1], pf[1][s], bf[i & 1]);
                }
            }
        }
        __syncthreads();
    }

    // ---- Epilogue: l lives in Osum col 64 (lanes with lane&3==0) ----
#pragma unroll
    for (int t = 0; t < 2; t++) {
        const float l0 = __shfl_sync(0xffffffffu, Osum[t][0], lane & 28);
        const float l1 = __shfl_sync(0xffffffffu, Osum[t][2], lane & 28);
        const float i0 = 1.f / l0, i1 = 1.f / l1;
        __half* Op = AO + ((size_t)b * Ss + q0 + 32 * wp + 16 * t + (lane >> 2)) * Dd
                   + h * DHh + pcol;
#pragma unroll
        for (int j = 0; j < 8; j++) {
            *(__half2*)(Op + 8 * j) =
                __floats2half2_rn(O[t][j][0] * i0, O[t][j][1] * i0);
            *(__half2*)(Op + 8 * (size_t)Dd + 8 * j) =
                __floats2half2_rn(O[t][j][2] * i1, O[t][j][3] * i1);
        }
    }
}

// ---------------------------------------------------------------------------
extern "C" void kernel_launch(void* const* d_in, const int* in_sizes, int n_in,
                              void* d_out, int out_size)
{
    (void)in_sizes; (void)n_in; (void)out_size;
    const float* seq  = (const float*)d_in[0];
    const float* mask = (const float*)d_in[1];
    const float* Wq   = (const float*)d_in[2];
    const float* bq   = (const float*)d_in[3];
    const float* Wk   = (const float*)d_in[4];
    const float* bk   = (const float*)d_in[5];
    const float* Wv   = (const float*)d_in[6];
    const float* bv   = (const float*)d_in[7];
    const float* Wo   = (const float*)d_in[8];
    const float* bo   = (const float*)d_in[9];
    float* out = (float*)d_out;

    __half *Qg, *Kg, *Vg, *AOg, *Xg, *Mg, *Wg;
    int* Fg;
    cudaGetSymbolAddress((void**)&Qg,  g_Q);
    cudaGetSymbolAddress((void**)&Kg,  g_K);
    cudaGetSymbolAddress((void**)&Vg,  g_V);
    cudaGetSymbolAddress((void**)&AOg, g_AO);
    cudaGetSymbolAddress((void**)&Xg,  g_X);
    cudaGetSymbolAddress((void**)&Mg,  g_maskh);
    cudaGetSymbolAddress((void**)&Wg,  g_Wh);
    cudaGetSymbolAddress((void**)&Fg,  g_mflag);

    cudaFuncSetAttribute(gemm_qkv,
                         cudaFuncAttributeMaxDynamicSharedMemorySize, GEMM_DSMEM);
    cudaFuncSetAttribute(gemm_out,
                         cudaFuncAttributeMaxDynamicSharedMemorySize, GEMM_DSMEM);

    const size_t WSZ = (size_t)Dd * Dd;

    // reset mask flag, then fp32 -> fp16 conversions (mask conv computes flag)
    cudaMemsetAsync(Fg, 0, sizeof(int));
    cvt_f2h<<<4096, 256>>>((const float4*)seq,  (__half2*)Xg,
                           (int)((size_t)Bb * Ss * Dd / 4));
    cvt_mask<<<8192, 256>>>((const float4*)mask, (__half2*)Mg,
                            (int)((size_t)Ss * Ss / 4));
    cvt_w4<<<dim3(144, 4), 256>>>((const float4*)Wq, (const float4*)Wk,
                                  (const float4*)Wv, (const float4*)Wo,
                                  (__half2*)Wg, (int)(WSZ / 4));

    // QKV projections (alpha_q = SCALE*log2e folded in)
    gemm_qkv<<<dim3(18, (Bb * Ss) / 128), 256, GEMM_DSMEM>>>(
        Xg, bq, bk, bv, Qg, Kg, Vg);

    // Flash attention: R8 config (2 CTAs/SM, grid (q_tile, bh))
    flash_f16<<<dim3(Ss / 128, Bb * Hh), 128>>>(Qg, Kg, Vg, Mg, AOg);

    // Output projection
    gemm_out<<<dim3(Dd / 128, (Bb * Ss) / 128), 256, GEMM_DSMEM>>>(AOg, bo, out);
}